// round 1
// baseline (speedup 1.0000x reference)
#include <cuda_runtime.h>
#include <math.h>

// ---------------- constants ----------------
#define NYRS_MAX 8192
#define W_YEARS  16            // warmup years for convergence of the contractive scan

#ifndef M_PI
#define M_PI 3.14159265358979323846
#endif

// ---------------- scratch (static device globals; no allocation) ----------------
__device__ float g_L[12];
__device__ float g_gE[12];
__device__ float g_Ep[NYRS_MAX * 12];
__device__ float g_width[NYRS_MAX];

__device__ __constant__ double c_NDAYS[13] = {0,31,28,31,30,31,30,31,31,30,31,30,31};
__device__ __constant__ int    c_CDAYS[13] = {0,31,59,90,120,151,181,212,243,273,304,334,365};

// ---------------- kernel 1: insolation factors (fp64 to match numpy) ----------------
__global__ void vsl_insolation_kernel(const int* __restrict__ phi_ptr) {
    __shared__ double sh_dtsi[365];
    __shared__ double sh_max;

    const double latr = (double)(*phi_ptr) * M_PI / 180.0;
    const int j = threadIdx.x;

    if (j < 365) {
        double jday = (double)(j + 1);
        double sd = asin(sin(M_PI * 23.5 / 180.0) * sin(M_PI * (jday - 80.0) / 180.0));
        double y  = -tan(latr) * tan(sd);
        y = fmin(fmax(y, -1.0), 1.0);
        double hdl = acos(y);
        double dtsi = hdl * sin(latr) * sin(sd) + cos(latr) * cos(sd) * sin(hdl);
        sh_dtsi[j] = dtsi;
    }
    __syncthreads();

    if (threadIdx.x == 0) {
        double mx = sh_dtsi[0];
        for (int i = 1; i < 365; i++) mx = fmax(mx, sh_dtsi[i]);
        sh_max = mx;
    }
    __syncthreads();

    if (threadIdx.x < 12) {
        const int t  = threadIdx.x;
        const int c0 = c_CDAYS[t];
        const int c1 = c_CDAYS[t + 1];
        double s = 0.0;
        for (int i = c0; i < c1; i++) s += sh_dtsi[i] / sh_max;
        g_gE[t] = (float)(s / (double)(c1 - c0));

        double jday_mid = (double)c0 + 0.5 * c_NDAYS[t + 1];
        double m_star = 1.0 - tan(latr) * tan(23.439 * M_PI / 180.0 * cos(jday_mid * M_PI / 182.625));
        m_star = fmin(fmax(m_star, 0.0), 2.0);
        double nhrs = 24.0 * acos(1.0 - m_star) / M_PI;
        g_L[t] = (float)(c_NDAYS[t + 1] / 30.0 * (nhrs / 12.0));
    }
}

// ---------------- kernel 2: Thornthwaite potential evapotranspiration ----------------
__global__ void vsl_potev_kernel(const float* __restrict__ T, int nyrs) {
    const int y = blockIdx.x * blockDim.x + threadIdx.x;
    if (y >= nyrs) return;

    float t[12];
    #pragma unroll
    for (int m = 0; m < 12; m++) t[m] = T[y * 12 + m];

    float I = 0.0f;
    #pragma unroll
    for (int m = 0; m < 12; m++) {
        float is = fmaxf(t[m] * 0.2f, 0.0f);     // T/5
        I += powf(is, 1.514f);
    }
    const float a = ((6.75e-7f * I - 7.71e-5f) * I + 0.0179f) * I + 0.49f;

    #pragma unroll
    for (int m = 0; m < 12; m++) {
        float Tm = t[m];
        float ep;
        if (Tm < 0.0f) {
            ep = 0.0f;
        } else if (Tm < 26.5f) {
            ep = 16.0f * g_L[m] * powf(10.0f * Tm / I, a);   // Tsafe == Tm on this branch
        } else {
            ep = -415.85f + 32.25f * Tm - 0.43f * Tm * Tm;
        }
        g_Ep[y * 12 + m] = ep;
    }
}

// ---------------- kernel 3: warm-started leaky-bucket scan + growth response ----------------
__global__ void vsl_scan_kernel(const float* __restrict__ T, const float* __restrict__ P,
                                const float* __restrict__ pT1, const float* __restrict__ pT2,
                                const float* __restrict__ pM1, const float* __restrict__ pM2,
                                int nyrs) {
    const int y = blockIdx.x * blockDim.x + threadIdx.x;
    if (y >= nyrs) return;

    const float T1 = *pT1, T2 = *pT2, M1 = *pM1, M2 = *pM2;
    const float invDT = 1.0f / (T2 - T1);
    const float invDM = 1.0f / (M2 - M1);

    const float invMMAX = 1.0f / 0.76f;
    const float C_G = 79.32352941176470f;   // MU_TH*ALPH/(1+MU_TH)*ROOTD
    const float C_R = 13.67647058823529f;   // ALPH/(1+MU_TH)*ROOTD

    const int start = (y > W_YEARS) ? (y - W_YEARS) : 0;
    float M = 0.2f;   // M0

    // warmup: converges to the true trajectory via contraction (factor <= 0.907/month)
    for (int idx = start * 12; idx < y * 12; idx++) {
        float p  = P[idx];
        float ep = g_Ep[idx];
        float r  = M * invMMAX;
        float pw = __powf(r, 4.886f);
        float dW = p - ep * r - (p * pw + C_R * M) - C_G * M;
        M = fminf(fmaxf(fmaf(dW, 0.001f, M), 0.01f), 0.76f);
    }

    // the real 12 months of year y
    float w = 0.0f;
    #pragma unroll
    for (int m = 0; m < 12; m++) {
        int idx = y * 12 + m;
        float p  = P[idx];
        float ep = g_Ep[idx];
        float r  = M * invMMAX;
        float pw = __powf(r, 4.886f);
        float dW = p - ep * r - (p * pw + C_R * M) - C_G * M;
        M = fminf(fmaxf(fmaf(dW, 0.001f, M), 0.01f), 0.76f);

        float gT = fminf(fmaxf((T[idx] - T1) * invDT, 0.0f), 1.0f);
        float gM = fminf(fmaxf((M     - M1) * invDM, 0.0f), 1.0f);
        w = fmaf(fminf(gT, gM), g_gE[m], w);
    }
    g_width[y] = w;
}

// ---------------- kernel 4: standardize (mean, unbiased std) ----------------
__global__ void vsl_normalize_kernel(float* __restrict__ out, int nyrs) {
    __shared__ double sh[1024];
    __shared__ double sh_mean, sh_inv;
    const int tid = threadIdx.x;
    const int nt = blockDim.x;

    double s = 0.0;
    for (int i = tid; i < nyrs; i += nt) s += (double)g_width[i];
    sh[tid] = s;
    __syncthreads();
    for (int o = nt >> 1; o > 0; o >>= 1) {
        if (tid < o) sh[tid] += sh[tid + o];
        __syncthreads();
    }
    if (tid == 0) sh_mean = sh[0] / (double)nyrs;
    __syncthreads();
    const double mean = sh_mean;
    __syncthreads();

    double ss = 0.0;
    for (int i = tid; i < nyrs; i += nt) {
        double d = (double)g_width[i] - mean;
        ss += d * d;
    }
    sh[tid] = ss;
    __syncthreads();
    for (int o = nt >> 1; o > 0; o >>= 1) {
        if (tid < o) sh[tid] += sh[tid + o];
        __syncthreads();
    }
    if (tid == 0) sh_inv = 1.0 / sqrt(sh[0] / (double)(nyrs - 1));
    __syncthreads();
    const double inv = sh_inv;

    for (int i = tid; i < nyrs; i += nt) {
        out[i] = (float)(((double)g_width[i] - mean) * inv);
    }
}

// ---------------- launch ----------------
extern "C" void kernel_launch(void* const* d_in, const int* in_sizes, int n_in,
                              void* d_out, int out_size) {
    // inputs: 0 syear(i32), 1 eyear(i32), 2 phi(i32), 3 T(f32 nyrs*12),
    //         4 P(f32 nyrs*12), 5 T1, 6 T2, 7 M1, 8 M2 (f32 scalars)
    const int*   phi = (const int*)d_in[2];
    const float* T   = (const float*)d_in[3];
    const float* P   = (const float*)d_in[4];
    const float* T1  = (const float*)d_in[5];
    const float* T2  = (const float*)d_in[6];
    const float* M1  = (const float*)d_in[7];
    const float* M2  = (const float*)d_in[8];
    float* out = (float*)d_out;

    const int nyrs = in_sizes[3] / 12;

    vsl_insolation_kernel<<<1, 384>>>(phi);
    vsl_potev_kernel<<<(nyrs + 127) / 128, 128>>>(T, nyrs);
    vsl_scan_kernel<<<(nyrs + 63) / 64, 64>>>(T, P, T1, T2, M1, M2, nyrs);
    vsl_normalize_kernel<<<1, 1024>>>(out, nyrs);
}

// round 3
// speedup vs baseline: 5.1057x; 5.1057x over previous
#include <cuda_runtime.h>
#include <math.h>

// ---------------- constants ----------------
#define NYRS_MAX 8192
#define W_YEARS  8             // warmup years (contraction ~e^-16 over 96 months)

#ifndef PI_F
#define PI_F 3.14159265358979323846f
#endif

// fast base-2 transcendentals via MUFU (explicit PTX; no fast-math flag needed)
__device__ __forceinline__ float fast_lg2(float x) {
    float r;
    asm("lg2.approx.f32 %0, %1;" : "=f"(r) : "f"(x));
    return r;
}
__device__ __forceinline__ float fast_ex2(float x) {
    float r;
    asm("ex2.approx.f32 %0, %1;" : "=f"(r) : "f"(x));
    return r;
}
__device__ __forceinline__ float fast_pow(float x, float e) {
    return fast_ex2(e * fast_lg2(x));
}

// ---------------- scratch (static device globals; no allocation) ----------------
__device__ float g_L[12];
__device__ float g_gE[12];
__device__ float g_A[NYRS_MAX * 12];   // per-month linear decay coefficient
__device__ float g_width[NYRS_MAX];

__device__ __constant__ float c_NDAYS[13] = {0,31,28,31,30,31,30,31,31,30,31,30,31};
__device__ __constant__ int   c_CDAYS[13] = {0,31,59,90,120,151,181,212,243,273,304,334,365};

// ---------------- kernel 1: insolation factors (all fp32) ----------------
__global__ void vsl_insolation_kernel(const int* __restrict__ phi_ptr) {
    __shared__ float sh_dtsi[365];
    __shared__ float sh_invmax;

    const float latr = (float)(*phi_ptr) * (PI_F / 180.0f);
    const int j = threadIdx.x;

    if (j < 365) {
        float jday = (float)(j + 1);
        float sd = asinf(sinf(PI_F * 23.5f / 180.0f) * sinf(PI_F * (jday - 80.0f) / 180.0f));
        float y  = -tanf(latr) * tanf(sd);
        y = fminf(fmaxf(y, -1.0f), 1.0f);
        float hdl = acosf(y);
        sh_dtsi[j] = hdl * sinf(latr) * sinf(sd) + cosf(latr) * cosf(sd) * sinf(hdl);
    }
    __syncthreads();

    // parallel max over 365 values: warp 0, each lane scans strided
    if (j < 32) {
        float mx = -1.0f;
        for (int i = j; i < 365; i += 32) mx = fmaxf(mx, sh_dtsi[i]);
        #pragma unroll
        for (int o = 16; o > 0; o >>= 1)
            mx = fmaxf(mx, __shfl_xor_sync(0xFFFFFFFF, mx, o));
        if (j == 0) sh_invmax = 1.0f / mx;
    }
    __syncthreads();

    if (j < 12) {
        const int t  = j;
        const int c0 = c_CDAYS[t];
        const int c1 = c_CDAYS[t + 1];
        float s = 0.0f;
        for (int i = c0; i < c1; i++) s += sh_dtsi[i];
        g_gE[t] = s * sh_invmax / (float)(c1 - c0);

        float jday_mid = (float)c0 + 0.5f * c_NDAYS[t + 1];
        float m_star = 1.0f - tanf(latr) * tanf(23.439f * PI_F / 180.0f * cosf(jday_mid * PI_F / 182.625f));
        m_star = fminf(fmaxf(m_star, 0.0f), 2.0f);
        float nhrs = 24.0f * acosf(1.0f - m_star) / PI_F;
        g_L[t] = c_NDAYS[t + 1] * (1.0f / 30.0f) * (nhrs * (1.0f / 12.0f));
    }
}

// ---------------- kernel 2: Thornthwaite PET -> per-month decay coeff A ----------------
// A[idx] = 0.907 - ep[idx] * (0.001/0.76); the full update is then
// M' = clamp(A*M + B - B*(M/0.76)^4.886), B = 0.001*p.
__global__ void vsl_potev_kernel(const float* __restrict__ T, int nyrs) {
    const int y = blockIdx.x * blockDim.x + threadIdx.x;
    if (y >= nyrs) return;

    float t[12];
    #pragma unroll
    for (int m = 0; m < 12; m++) t[m] = T[y * 12 + m];

    float I = 0.0f;
    #pragma unroll
    for (int m = 0; m < 12; m++) {
        float is = fmaxf(t[m] * 0.2f, 0.0f);     // T/5
        if (is > 0.0f) I += fast_pow(is, 1.514f);
    }
    const float a = ((6.75e-7f * I - 7.71e-5f) * I + 0.0179f) * I + 0.49f;
    const float invI = 1.0f / I;

    #pragma unroll
    for (int m = 0; m < 12; m++) {
        float Tm = t[m];
        float ep;
        if (Tm < 0.0f) {
            ep = 0.0f;
        } else if (Tm < 26.5f) {
            ep = 16.0f * g_L[m] * fast_pow(10.0f * Tm * invI, a);
        } else {
            ep = -415.85f + 32.25f * Tm - 0.43f * Tm * Tm;
        }
        g_A[y * 12 + m] = 0.907f - ep * 1.31578947e-3f;
    }
}

// ---------------- kernel 3: warm-started leaky-bucket scan + growth response ----------------
__global__ void vsl_scan_kernel(const float* __restrict__ T, const float* __restrict__ P,
                                const float* __restrict__ pT1, const float* __restrict__ pT2,
                                const float* __restrict__ pM1, const float* __restrict__ pM2,
                                int nyrs) {
    const int y = blockIdx.x * blockDim.x + threadIdx.x;
    if (y >= nyrs) return;

    const float T1 = *pT1, T2 = *pT2, M1 = *pM1, M2 = *pM2;
    const float invDT = 1.0f / (T2 - T1);
    const float invDM = 1.0f / (M2 - M1);

    // (M/0.76)^4.886 = exp2(4.886*log2(M) + 4.886*log2(1/0.76))
    const float PEXP = 4.886f;
    const float POFF = 1.93446714f;   // 4.886 * log2(1/0.76)

    const int start = (y > W_YEARS) ? (y - W_YEARS) : 0;
    float M = 0.2f;   // M0

    // warmup: contraction erases the M0 guess (factor ~0.84/month typical)
    for (int idx = start * 12; idx < y * 12; idx++) {
        float A  = g_A[idx];
        float B  = P[idx] * 0.001f;
        float pw = fast_ex2(fmaf(PEXP, fast_lg2(M), POFF));
        float t  = fmaf(A, M, B);          // off critical path of pw
        M = fminf(fmaxf(fmaf(-B, pw, t), 0.01f), 0.76f);
    }

    // the real 12 months of year y
    float w = 0.0f;
    #pragma unroll
    for (int m = 0; m < 12; m++) {
        int idx = y * 12 + m;
        float A  = g_A[idx];
        float B  = P[idx] * 0.001f;
        float pw = fast_ex2(fmaf(PEXP, fast_lg2(M), POFF));
        float t  = fmaf(A, M, B);
        M = fminf(fmaxf(fmaf(-B, pw, t), 0.01f), 0.76f);

        float gT = fminf(fmaxf((T[idx] - T1) * invDT, 0.0f), 1.0f);
        float gM = fminf(fmaxf((M     - M1) * invDM, 0.0f), 1.0f);
        w = fmaf(fminf(gT, gM), g_gE[m], w);
    }
    g_width[y] = w;
}

// ---------------- kernel 4: standardize (fp32, two-pass, warp shuffles) ----------------
__global__ void vsl_normalize_kernel(float* __restrict__ out, int nyrs) {
    __shared__ float sh[32];
    __shared__ float sh_bcast;
    const int tid  = threadIdx.x;
    const int nt   = blockDim.x;
    const int lane = tid & 31;
    const int wid  = tid >> 5;
    const int nw   = nt >> 5;

    // pass 1: mean
    float s = 0.0f;
    for (int i = tid; i < nyrs; i += nt) s += g_width[i];
    #pragma unroll
    for (int o = 16; o > 0; o >>= 1) s += __shfl_xor_sync(0xFFFFFFFF, s, o);
    if (lane == 0) sh[wid] = s;
    __syncthreads();
    if (wid == 0) {
        float v = (lane < nw) ? sh[lane] : 0.0f;
        #pragma unroll
        for (int o = 16; o > 0; o >>= 1) v += __shfl_xor_sync(0xFFFFFFFF, v, o);
        if (lane == 0) sh_bcast = v / (float)nyrs;
    }
    __syncthreads();
    const float mean = sh_bcast;
    __syncthreads();

    // pass 2: variance (unbiased)
    float ss = 0.0f;
    for (int i = tid; i < nyrs; i += nt) {
        float d = g_width[i] - mean;
        ss = fmaf(d, d, ss);
    }
    #pragma unroll
    for (int o = 16; o > 0; o >>= 1) ss += __shfl_xor_sync(0xFFFFFFFF, ss, o);
    if (lane == 0) sh[wid] = ss;
    __syncthreads();
    if (wid == 0) {
        float v = (lane < nw) ? sh[lane] : 0.0f;
        #pragma unroll
        for (int o = 16; o > 0; o >>= 1) v += __shfl_xor_sync(0xFFFFFFFF, v, o);
        if (lane == 0) sh_bcast = rsqrtf(v / (float)(nyrs - 1));
    }
    __syncthreads();
    const float inv = sh_bcast;

    for (int i = tid; i < nyrs; i += nt)
        out[i] = (g_width[i] - mean) * inv;
}

// ---------------- launch ----------------
extern "C" void kernel_launch(void* const* d_in, const int* in_sizes, int n_in,
                              void* d_out, int out_size) {
    // inputs: 0 syear(i32), 1 eyear(i32), 2 phi(i32), 3 T(f32 nyrs*12),
    //         4 P(f32 nyrs*12), 5 T1, 6 T2, 7 M1, 8 M2 (f32 scalars)
    const int*   phi = (const int*)d_in[2];
    const float* T   = (const float*)d_in[3];
    const float* P   = (const float*)d_in[4];
    const float* T1  = (const float*)d_in[5];
    const float* T2  = (const float*)d_in[6];
    const float* M1  = (const float*)d_in[7];
    const float* M2  = (const float*)d_in[8];
    float* out = (float*)d_out;

    const int nyrs = in_sizes[3] / 12;

    vsl_insolation_kernel<<<1, 384>>>(phi);
    vsl_potev_kernel<<<(nyrs + 127) / 128, 128>>>(T, nyrs);
    vsl_scan_kernel<<<(nyrs + 63) / 64, 64>>>(T, P, T1, T2, M1, M2, nyrs);
    vsl_normalize_kernel<<<1, 1024>>>(out, nyrs);
}

// round 4
// speedup vs baseline: 6.1697x; 1.2084x over previous
#include <cuda_runtime.h>
#include <math.h>

#define NYRS_MAX 8192
#define YPB      256          // years per block
#define W_YEARS  8            // warmup years
#define WMONTHS  (W_YEARS * 12)

#define PI_F 3.14159265358979323846f

// fast base-2 transcendentals via MUFU
__device__ __forceinline__ float fast_lg2(float x) {
    float r; asm("lg2.approx.f32 %0, %1;" : "=f"(r) : "f"(x)); return r;
}
__device__ __forceinline__ float fast_ex2(float x) {
    float r; asm("ex2.approx.f32 %0, %1;" : "=f"(r) : "f"(x)); return r;
}
__device__ __forceinline__ float fast_pow(float x, float e) {
    return fast_ex2(e * fast_lg2(x));
}

// ---------------- device state (no allocation) ----------------
__device__ float        g_width[NYRS_MAX];
__device__ unsigned int g_ticket = 0;

__device__ __constant__ float c_NDAYS[13] = {0,31,28,31,30,31,30,31,31,30,31,30,31};
__device__ __constant__ int   c_CDAYS[13] = {0,31,59,90,120,151,181,212,243,273,304,334,365};

__global__ void __launch_bounds__(YPB, 1)
vsl_fused_kernel(const int* __restrict__ phi_ptr,
                 const float* __restrict__ T, const float* __restrict__ P,
                 const float* __restrict__ pT1, const float* __restrict__ pT2,
                 const float* __restrict__ pM1, const float* __restrict__ pM2,
                 float* __restrict__ out, int nyrs) {
    __shared__ float sh_dtsi[365];
    __shared__ float sh_invmax;
    __shared__ float sh_L[12];
    __shared__ float sh_gE[12];
    __shared__ float sh_A[(YPB + W_YEARS) * 12];
    __shared__ float sh_B[(YPB + W_YEARS) * 12];
    __shared__ float sh_red[8];
    __shared__ float sh_bcast;
    __shared__ unsigned int sh_last;

    const int tid     = threadIdx.x;
    const int blockY0 = blockIdx.x * YPB;
    const float latr  = (float)(*phi_ptr) * (PI_F / 180.0f);

    // ---- stage 1: daily insolation (redundant per block, MUFU sin/tan) ----
    const float tlat = __tanf(latr);
    const float slat = __sinf(latr);
    const float clat = __cosf(latr);
    for (int j = tid; j < 365; j += YPB) {
        float jday = (float)(j + 1);
        float sd = asinf(0.39874907f * __sinf(PI_F * (jday - 80.0f) * (1.0f / 180.0f)));
        float y  = fminf(fmaxf(-tlat * __tanf(sd), -1.0f), 1.0f);
        float hdl = acosf(y);
        sh_dtsi[j] = hdl * slat * __sinf(sd) + clat * __cosf(sd) * __sinf(hdl);
    }
    __syncthreads();

    if (tid < 32) {
        float mx = -1.0f;
        for (int i = tid; i < 365; i += 32) mx = fmaxf(mx, sh_dtsi[i]);
        #pragma unroll
        for (int o = 16; o > 0; o >>= 1)
            mx = fmaxf(mx, __shfl_xor_sync(0xFFFFFFFF, mx, o));
        if (tid == 0) sh_invmax = 1.0f / mx;
    }
    __syncthreads();

    if (tid < 12) {
        const int c0 = c_CDAYS[tid];
        const int c1 = c_CDAYS[tid + 1];
        float s = 0.0f;
        for (int i = c0; i < c1; i++) s += sh_dtsi[i];
        sh_gE[tid] = s * sh_invmax / (float)(c1 - c0);

        float jday_mid = (float)c0 + 0.5f * c_NDAYS[tid + 1];
        float m_star = 1.0f - tlat * __tanf(0.40908772f * __cosf(jday_mid * (PI_F / 182.625f)));
        m_star = fminf(fmaxf(m_star, 0.0f), 2.0f);
        float nhrs = 24.0f * acosf(1.0f - m_star) * (1.0f / PI_F);
        sh_L[tid] = c_NDAYS[tid + 1] * (1.0f / 30.0f) * (nhrs * (1.0f / 12.0f));
    }
    __syncthreads();

    // ---- stage 2: PET -> (A, B) for this block's years + 8-year halo ----
    // update: M' = clamp(A*M + B*(1 - (M/0.76)^4.886)),  A = 0.907 - ep*(0.001/0.76), B = p/1000
    for (int s = tid; s < YPB + W_YEARS; s += YPB) {
        const int yy = blockY0 - W_YEARS + s;
        if (yy < 0 || yy >= nyrs) {
            #pragma unroll
            for (int m = 0; m < 12; m++) { sh_A[s*12 + m] = 1.0f; sh_B[s*12 + m] = 0.0f; }
        } else {
            float t[12];
            #pragma unroll
            for (int m = 0; m < 12; m++) t[m] = T[yy*12 + m];

            float I = 0.0f;
            #pragma unroll
            for (int m = 0; m < 12; m++) {
                float is = t[m] * 0.2f;
                if (is > 0.0f) I += fast_pow(is, 1.514f);
            }
            const float a = ((6.75e-7f * I - 7.71e-5f) * I + 0.0179f) * I + 0.49f;
            const float invI = 1.0f / I;

            #pragma unroll
            for (int m = 0; m < 12; m++) {
                float Tm = t[m];
                float ep;
                if (Tm < 0.0f)        ep = 0.0f;
                else if (Tm < 26.5f)  ep = 16.0f * sh_L[m] * fast_pow(10.0f * Tm * invI, a);
                else                  ep = -415.85f + 32.25f * Tm - 0.43f * Tm * Tm;
                sh_A[s*12 + m] = 0.907f - ep * 1.31578947e-3f;
                sh_B[s*12 + m] = P[yy*12 + m] * 0.001f;
            }
        }
    }
    __syncthreads();

    // ---- stage 3: warm-started chain + growth response ----
    const int y = blockY0 + tid;
    if (y < nyrs) {
        const float T1 = *pT1, T2 = *pT2, M1 = *pM1, M2 = *pM2;
        const float invDT = 1.0f / (T2 - T1);
        const float invDM = 1.0f / (M2 - M1);
        const float PEXP = 4.886f;
        const float POFF = 1.9345074f;   // 4.886 * log2(1/0.76)

        const float* sA = sh_A + tid * 12;
        const float* sB = sh_B + tid * 12;
        float M = 0.2f;

        #pragma unroll 4
        for (int i = 0; i < WMONTHS; i++) {
            float A  = sA[i];
            float B  = sB[i];
            float pw = fast_ex2(fmaf(PEXP, fast_lg2(M), POFF));
            float t  = fmaf(A, M, B);
            M = fminf(fmaxf(fmaf(-B, pw, t), 0.01f), 0.76f);
        }

        float w = 0.0f;
        #pragma unroll
        for (int m = 0; m < 12; m++) {
            float A  = sA[WMONTHS + m];
            float B  = sB[WMONTHS + m];
            float pw = fast_ex2(fmaf(PEXP, fast_lg2(M), POFF));
            float t  = fmaf(A, M, B);
            M = fminf(fmaxf(fmaf(-B, pw, t), 0.01f), 0.76f);

            float gT = fminf(fmaxf((T[y*12 + m] - T1) * invDT, 0.0f), 1.0f);
            float gM = fminf(fmaxf((M           - M1) * invDM, 0.0f), 1.0f);
            w = fmaf(fminf(gT, gM), sh_gE[m], w);
        }
        g_width[y] = w;
    }

    // ---- stage 4: last block standardizes ----
    __syncthreads();
    __threadfence();
    if (tid == 0) sh_last = (atomicAdd(&g_ticket, 1u) == gridDim.x - 1u);
    __syncthreads();
    if (!sh_last) return;

    const int lane = tid & 31;
    const int wid  = tid >> 5;
    const int PER  = NYRS_MAX / YPB;   // 32

    float v[PER];
    float s = 0.0f;
    int cnt = 0;
    #pragma unroll
    for (int i = 0; i < PER; i++) {
        int idx = tid + i * YPB;
        v[i] = (idx < nyrs) ? __ldcg(&g_width[idx]) : 0.0f;
        if (idx < nyrs) { s += v[i]; cnt = i + 1; }
    }
    #pragma unroll
    for (int o = 16; o > 0; o >>= 1) s += __shfl_xor_sync(0xFFFFFFFF, s, o);
    if (lane == 0) sh_red[wid] = s;
    __syncthreads();
    if (wid == 0) {
        float t = (lane < 8) ? sh_red[lane] : 0.0f;
        #pragma unroll
        for (int o = 4; o > 0; o >>= 1) t += __shfl_xor_sync(0xFFFFFFFF, t, o);
        if (lane == 0) sh_bcast = t / (float)nyrs;
    }
    __syncthreads();
    const float mean = sh_bcast;
    __syncthreads();

    float ss = 0.0f;
    #pragma unroll
    for (int i = 0; i < PER; i++) {
        if (i < cnt) { float d = v[i] - mean; ss = fmaf(d, d, ss); }
    }
    #pragma unroll
    for (int o = 16; o > 0; o >>= 1) ss += __shfl_xor_sync(0xFFFFFFFF, ss, o);
    if (lane == 0) sh_red[wid] = ss;
    __syncthreads();
    if (wid == 0) {
        float t = (lane < 8) ? sh_red[lane] : 0.0f;
        #pragma unroll
        for (int o = 4; o > 0; o >>= 1) t += __shfl_xor_sync(0xFFFFFFFF, t, o);
        if (lane == 0) sh_bcast = rsqrtf(t / (float)(nyrs - 1));
    }
    __syncthreads();
    const float inv = sh_bcast;

    #pragma unroll
    for (int i = 0; i < PER; i++) {
        int idx = tid + i * YPB;
        if (idx < nyrs) out[idx] = (v[i] - mean) * inv;
    }

    if (tid == 0) g_ticket = 0;   // reset for next graph replay
}

// ---------------- launch ----------------
extern "C" void kernel_launch(void* const* d_in, const int* in_sizes, int n_in,
                              void* d_out, int out_size) {
    const int*   phi = (const int*)d_in[2];
    const float* T   = (const float*)d_in[3];
    const float* P   = (const float*)d_in[4];
    const float* T1  = (const float*)d_in[5];
    const float* T2  = (const float*)d_in[6];
    const float* M1  = (const float*)d_in[7];
    const float* M2  = (const float*)d_in[8];
    float* out = (float*)d_out;

    const int nyrs = in_sizes[3] / 12;
    const int nblk = (nyrs + YPB - 1) / YPB;

    vsl_fused_kernel<<<nblk, YPB>>>(phi, T, P, T1, T2, M1, M2, out, nyrs);
}

// round 5
// speedup vs baseline: 6.2220x; 1.0085x over previous
#include <cuda_runtime.h>
#include <math.h>

#define NYRS_MAX 8192
#define YPB      256                 // years per block
#define W_YEARS  6                   // warmup years
#define WMONTHS  (W_YEARS * 12)
#define SLOTS    (YPB + W_YEARS)     // 262 year-slots incl. halo

#define PI_F 3.14159265358979323846f

__device__ __forceinline__ float fast_lg2(float x) {
    float r; asm("lg2.approx.f32 %0, %1;" : "=f"(r) : "f"(x)); return r;
}
__device__ __forceinline__ float fast_ex2(float x) {
    float r; asm("ex2.approx.f32 %0, %1;" : "=f"(r) : "f"(x)); return r;
}
__device__ __forceinline__ float fast_pow(float x, float e) {
    return fast_ex2(e * fast_lg2(x));
}

// ---------------- device state (no allocation) ----------------
__device__ float        g_width[NYRS_MAX];
__device__ unsigned int g_ticket = 0;

__device__ __constant__ float c_NDAYS[13] = {0,31,28,31,30,31,30,31,31,30,31,30,31};
__device__ __constant__ int   c_CDAYS[13] = {0,31,59,90,120,151,181,212,243,273,304,334,365};

__global__ void __launch_bounds__(YPB, 1)
vsl_fused_kernel(const int* __restrict__ phi_ptr,
                 const float* __restrict__ T, const float* __restrict__ P,
                 const float* __restrict__ pT1, const float* __restrict__ pT2,
                 const float* __restrict__ pM1, const float* __restrict__ pM2,
                 float* __restrict__ out, int nyrs) {
    __shared__ float sh_dtsi[365];
    __shared__ float sh_invmax;
    __shared__ float sh_L[12];
    __shared__ float sh_gE[12];
    __shared__ float sh_A [12 * SLOTS];   // month-major: [m][slot] -> conflict-free LDS
    __shared__ float sh_B [12 * SLOTS];
    __shared__ float sh_gT[12 * SLOTS];
    __shared__ float sh_red[8];
    __shared__ float sh_bcast;
    __shared__ unsigned int sh_last;

    const int tid     = threadIdx.x;
    const int blockY0 = blockIdx.x * YPB;
    const float latr  = (float)(*phi_ptr) * (PI_F / 180.0f);
    const float T1 = *pT1, T2 = *pT2, M1 = *pM1, M2 = *pM2;
    const float invDT = 1.0f / (T2 - T1);
    const float invDM = 1.0f / (M2 - M1);

    // ---- stage 1: daily insolation (redundant per block) ----
    const float tlat = __tanf(latr);
    const float slat = __sinf(latr);
    const float clat = __cosf(latr);
    for (int j = tid; j < 365; j += YPB) {
        float jday = (float)(j + 1);
        float sd = asinf(0.39874907f * __sinf(PI_F * (jday - 80.0f) * (1.0f / 180.0f)));
        float y  = fminf(fmaxf(-tlat * __tanf(sd), -1.0f), 1.0f);
        float hdl = acosf(y);
        sh_dtsi[j] = hdl * slat * __sinf(sd) + clat * __cosf(sd) * __sinf(hdl);
    }
    __syncthreads();

    if (tid < 32) {
        float mx = -1.0f;
        for (int i = tid; i < 365; i += 32) mx = fmaxf(mx, sh_dtsi[i]);
        #pragma unroll
        for (int o = 16; o > 0; o >>= 1)
            mx = fmaxf(mx, __shfl_xor_sync(0xFFFFFFFF, mx, o));
        if (tid == 0) sh_invmax = 1.0f / mx;
    }
    __syncthreads();

    if (tid < 12) {
        const int c0 = c_CDAYS[tid];
        const int c1 = c_CDAYS[tid + 1];
        float s = 0.0f;
        for (int i = c0; i < c1; i++) s += sh_dtsi[i];
        sh_gE[tid] = s * sh_invmax / (float)(c1 - c0);

        float jday_mid = (float)c0 + 0.5f * c_NDAYS[tid + 1];
        float m_star = 1.0f - tlat * __tanf(0.40908772f * __cosf(jday_mid * (PI_F / 182.625f)));
        m_star = fminf(fmaxf(m_star, 0.0f), 2.0f);
        float nhrs = 24.0f * acosf(1.0f - m_star) * (1.0f / PI_F);
        sh_L[tid] = c_NDAYS[tid + 1] * (1.0f / 30.0f) * (nhrs * (1.0f / 12.0f));
    }
    __syncthreads();

    // ---- stage 2: PET -> (A, B, gT), month-major shared ----
    // M' = clamp(A*M + B - B*(M/0.76)^4.886),  A = 0.907 - ep*(0.001/0.76), B = p/1000
    for (int s = tid; s < SLOTS; s += YPB) {
        const int yy = blockY0 - W_YEARS + s;
        if (yy < 0 || yy >= nyrs) {
            #pragma unroll
            for (int m = 0; m < 12; m++) {
                sh_A [m*SLOTS + s] = 1.0f;   // identity step: M stays put (exact for y < W)
                sh_B [m*SLOTS + s] = 0.0f;
                sh_gT[m*SLOTS + s] = 0.0f;
            }
        } else {
            float t[12];
            #pragma unroll
            for (int m = 0; m < 12; m++) t[m] = T[yy*12 + m];

            float I = 0.0f;
            #pragma unroll
            for (int m = 0; m < 12; m++) {
                float is = t[m] * 0.2f;
                if (is > 0.0f) I += fast_pow(is, 1.514f);
            }
            const float a = ((6.75e-7f * I - 7.71e-5f) * I + 0.0179f) * I + 0.49f;
            const float invI = 1.0f / I;

            #pragma unroll
            for (int m = 0; m < 12; m++) {
                float Tm = t[m];
                float ep;
                if (Tm < 0.0f)        ep = 0.0f;
                else if (Tm < 26.5f)  ep = 16.0f * sh_L[m] * fast_pow(10.0f * Tm * invI, a);
                else                  ep = -415.85f + 32.25f * Tm - 0.43f * Tm * Tm;
                sh_A [m*SLOTS + s] = 0.907f - ep * 1.31578947e-3f;
                sh_B [m*SLOTS + s] = P[yy*12 + m] * 0.001f;
                sh_gT[m*SLOTS + s] = fminf(fmaxf((Tm - T1) * invDT, 0.0f), 1.0f);
            }
        }
    }
    __syncthreads();

    // ---- stage 3: warm-started chain + growth response (pure shared/register) ----
    const int y = blockY0 + tid;
    if (y < nyrs) {
        const float PEXP = 4.886f;
        const float POFF = 1.9345078f;        // 4.886 * log2(1/0.76)
        const float M1s  = M1 * invDM;

        float M = 0.2f;

        // warmup: W_YEARS years, slot constant per unrolled year -> LDS hoisting
        #pragma unroll
        for (int j = 0; j < W_YEARS; j++) {
            const int s = tid + j;
            #pragma unroll
            for (int m = 0; m < 12; m++) {
                float A  = sh_A[m*SLOTS + s];
                float B  = sh_B[m*SLOTS + s];
                float pw = fast_ex2(fmaf(PEXP, fast_lg2(M), POFF));
                float t  = fmaf(A, M, B);
                M = fminf(fmaxf(fmaf(-B, pw, t), 0.01f), 0.76f);
            }
        }

        // the real 12 months
        float w = 0.0f;
        {
            const int s = tid + W_YEARS;
            #pragma unroll
            for (int m = 0; m < 12; m++) {
                float A  = sh_A[m*SLOTS + s];
                float B  = sh_B[m*SLOTS + s];
                float pw = fast_ex2(fmaf(PEXP, fast_lg2(M), POFF));
                float t  = fmaf(A, M, B);
                M = fminf(fmaxf(fmaf(-B, pw, t), 0.01f), 0.76f);

                float gM = fminf(fmaxf(fmaf(M, invDM, -M1s), 0.0f), 1.0f);
                float gT = sh_gT[m*SLOTS + s];
                w = fmaf(fminf(gT, gM), sh_gE[m], w);
            }
        }
        g_width[y] = w;
    }

    // ---- stage 4: last block standardizes ----
    __threadfence();
    __syncthreads();
    if (tid == 0) sh_last = (atomicAdd(&g_ticket, 1u) == gridDim.x - 1u);
    __syncthreads();
    if (!sh_last) return;

    const int lane = tid & 31;
    const int wid  = tid >> 5;
    const int PER  = NYRS_MAX / YPB;   // 32

    float v[PER];
    float s = 0.0f;
    int cnt = 0;
    #pragma unroll
    for (int i = 0; i < PER; i++) {
        int idx = tid + i * YPB;
        v[i] = (idx < nyrs) ? __ldcg(&g_width[idx]) : 0.0f;
        if (idx < nyrs) { s += v[i]; cnt = i + 1; }
    }
    #pragma unroll
    for (int o = 16; o > 0; o >>= 1) s += __shfl_xor_sync(0xFFFFFFFF, s, o);
    if (lane == 0) sh_red[wid] = s;
    __syncthreads();
    if (wid == 0) {
        float t = (lane < 8) ? sh_red[lane] : 0.0f;
        #pragma unroll
        for (int o = 4; o > 0; o >>= 1) t += __shfl_xor_sync(0xFFFFFFFF, t, o);
        if (lane == 0) sh_bcast = t / (float)nyrs;
    }
    __syncthreads();
    const float mean = sh_bcast;
    __syncthreads();

    float ss = 0.0f;
    #pragma unroll
    for (int i = 0; i < PER; i++) {
        if (i < cnt) { float d = v[i] - mean; ss = fmaf(d, d, ss); }
    }
    #pragma unroll
    for (int o = 16; o > 0; o >>= 1) ss += __shfl_xor_sync(0xFFFFFFFF, ss, o);
    if (lane == 0) sh_red[wid] = ss;
    __syncthreads();
    if (wid == 0) {
        float t = (lane < 8) ? sh_red[lane] : 0.0f;
        #pragma unroll
        for (int o = 4; o > 0; o >>= 1) t += __shfl_xor_sync(0xFFFFFFFF, t, o);
        if (lane == 0) sh_bcast = rsqrtf(t / (float)(nyrs - 1));
    }
    __syncthreads();
    const float inv = sh_bcast;

    #pragma unroll
    for (int i = 0; i < PER; i++) {
        int idx = tid + i * YPB;
        if (idx < nyrs) out[idx] = (v[i] - mean) * inv;
    }

    if (tid == 0) g_ticket = 0;   // reset for next graph replay
}

// ---------------- launch ----------------
extern "C" void kernel_launch(void* const* d_in, const int* in_sizes, int n_in,
                              void* d_out, int out_size) {
    const int*   phi = (const int*)d_in[2];
    const float* T   = (const float*)d_in[3];
    const float* P   = (const float*)d_in[4];
    const float* T1  = (const float*)d_in[5];
    const float* T2  = (const float*)d_in[6];
    const float* M1  = (const float*)d_in[7];
    const float* M2  = (const float*)d_in[8];
    float* out = (float*)d_out;

    const int nyrs = in_sizes[3] / 12;
    const int nblk = (nyrs + YPB - 1) / YPB;

    vsl_fused_kernel<<<nblk, YPB>>>(phi, T, P, T1, T2, M1, M2, out, nyrs);
}